// round 7
// baseline (speedup 1.0000x reference)
#include <cuda_runtime.h>
#include <cstdint>

// ---------------------------------------------------------------------------
// MultiHeadAttention B=2,S=2048,D=1024,H=16,Dh=64 fp32 — R7:
//  * GEMMs: 8 warps, 64x32/warp, CF strides (As 36 / Bs 136), 2 blocks/SM
//  * Attention: 512 threads (16 warps x m16n64), 256 q-rows, 2-stage KV
// ---------------------------------------------------------------------------

constexpr int BB = 2;
constexpr int SS = 2048;
constexpr int DD = 1024;
constexpr int HH = 16;
constexpr int DH = 64;
constexpr int MT = BB * SS;   // 4096

__device__ float g_q[BB * HH * SS * DH];
__device__ float g_k[BB * HH * SS * DH];
__device__ float g_v[BB * HH * SS * DH];
__device__ float g_att[MT * DD];
__device__ float g_xt[MT * DD];
__device__ float g_wqt[DD * DD];
__device__ float g_wkt[DD * DD];
__device__ float g_wvt[DD * DD];
__device__ float g_wot[DD * DD];

__device__ __forceinline__ uint32_t f2tf(float x) {
    uint32_t r;
    asm("cvt.rna.tf32.f32 %0, %1;" : "=r"(r) : "f"(x));
    return r;
}
__device__ __forceinline__ void mma8(float* d, uint32_t a0, uint32_t a1,
                                     uint32_t a2, uint32_t a3,
                                     uint32_t b0, uint32_t b1) {
    asm volatile(
        "mma.sync.aligned.m16n8k8.row.col.f32.tf32.tf32.f32 "
        "{%0,%1,%2,%3}, {%4,%5,%6,%7}, {%8,%9}, {%0,%1,%2,%3};"
        : "+f"(d[0]), "+f"(d[1]), "+f"(d[2]), "+f"(d[3])
        : "r"(a0), "r"(a1), "r"(a2), "r"(a3), "r"(b0), "r"(b1));
}
__device__ __forceinline__ void cp16(uint32_t dst, const void* src) {
    asm volatile("cp.async.cg.shared.global [%0], [%1], 16;"
                 :: "r"(dst), "l"(src));
}
__device__ __forceinline__ void cp_commit() {
    asm volatile("cp.async.commit_group;");
}
template <int N>
__device__ __forceinline__ void cp_wait() {
    asm volatile("cp.async.wait_group %0;" :: "n"(N));
}
__device__ __forceinline__ float4 cvt4(float4 v) {
    float4 o;
    o.x = __uint_as_float(f2tf(v.x));
    o.y = __uint_as_float(f2tf(v.y));
    o.z = __uint_as_float(f2tf(v.z));
    o.w = __uint_as_float(f2tf(v.w));
    return o;
}

// ---------------------------------------------------------------------------
// K0: pre-round x, wq, wk, wv, wo.
// ---------------------------------------------------------------------------
__global__ __launch_bounds__(256) void cvt_inputs(
    const float* __restrict__ x,
    const float* __restrict__ wq, const float* __restrict__ wk,
    const float* __restrict__ wv, const float* __restrict__ wo)
{
    const int z = blockIdx.y;
    const float* src = (z == 0) ? x : (z == 1) ? wq : (z == 2) ? wk
                       : (z == 3) ? wv : wo;
    float* dst = (z == 0) ? g_xt : (z == 1) ? g_wqt : (z == 2) ? g_wkt
                 : (z == 3) ? g_wvt : g_wot;
    const int n4 = ((z == 0) ? MT * DD : DD * DD) >> 2;
    const float4* s4 = reinterpret_cast<const float4*>(src);
    float4* d4 = reinterpret_cast<float4*>(dst);
    for (int i = blockIdx.x * blockDim.x + threadIdx.x; i < n4;
         i += gridDim.x * blockDim.x)
        d4[i] = cvt4(s4[i]);
}

// ---------------------------------------------------------------------------
// GEMM: 128x128 tile, BK=32, 8 warps (2x4), 64x32 per warp, 3-stage cp.async.
// As [128][36], Bs [32][136] — both conflict-free on fragment reads.
// ---------------------------------------------------------------------------
constexpr int AS_ELEM = 128 * 36;   // 4608
constexpr int BS_ELEM = 32 * 136;   // 4352
constexpr int GEMM_SMEM = 3 * (AS_ELEM + BS_ELEM) * (int)sizeof(float); // 107520

__device__ __forceinline__ void gemm_stage(
    uint32_t As_s, uint32_t Bs_s, int s, const float* __restrict__ A,
    const float* __restrict__ B, int brow, int bcol, int kk, int tid)
{
#pragma unroll
    for (int i = 0; i < 4; i++) {
        int idx = tid + (i << 8);
        int r = idx >> 3, c4 = (idx & 7) << 2;
        cp16(As_s + (s * AS_ELEM + r * 36 + c4) * 4,
             A + (size_t)(brow + r) * DD + kk + c4);
    }
#pragma unroll
    for (int i = 0; i < 4; i++) {
        int idx = tid + (i << 8);
        int r = idx >> 5, c4 = (idx & 31) << 2;
        cp16(Bs_s + (s * BS_ELEM + r * 136 + c4) * 4,
             B + (size_t)(kk + r) * DD + bcol + c4);
    }
    cp_commit();
}

__device__ __forceinline__ void gemm_compute(
    const float* As, const float* Bs, int lane, int wm, int wn,
    float acc[4][4][4])
{
    const int ar = wm * 64 + (lane >> 2);
    const int bc = wn * 32 + (lane >> 2);
#pragma unroll
    for (int ks = 0; ks < 4; ks++) {
        const int k0 = ks * 8;
        uint32_t a[4][4], b[4][2];
        const int acl = k0 + (lane & 3);
#pragma unroll
        for (int mi = 0; mi < 4; mi++) {
            const float* p = &As[(ar + mi * 16) * 36 + acl];
            a[mi][0] = __float_as_uint(p[0]);
            a[mi][2] = __float_as_uint(p[4]);
            a[mi][1] = __float_as_uint(p[8 * 36]);
            a[mi][3] = __float_as_uint(p[8 * 36 + 4]);
        }
        const int br = k0 + (lane & 3);
#pragma unroll
        for (int ni = 0; ni < 4; ni++) {
            const float* p = &Bs[br * 136 + bc + ni * 8];
            b[ni][0] = __float_as_uint(p[0]);
            b[ni][1] = __float_as_uint(p[4 * 136]);
        }
#pragma unroll
        for (int mi = 0; mi < 4; mi++)
#pragma unroll
            for (int ni = 0; ni < 4; ni++)
                mma8(acc[mi][ni], a[mi][0], a[mi][1], a[mi][2], a[mi][3],
                     b[ni][0], b[ni][1]);
    }
}

template <typename EpiF>
__device__ __forceinline__ void gemm_run(
    float* sm, const float* __restrict__ A, const float* __restrict__ B,
    int brow, int bcol, EpiF epi)
{
    const uint32_t As_s = (uint32_t)__cvta_generic_to_shared(sm);
    const uint32_t Bs_s = (uint32_t)__cvta_generic_to_shared(sm + 3 * AS_ELEM);
    const float* AsB = sm;
    const float* BsB = sm + 3 * AS_ELEM;

    const int tid = threadIdx.x;
    const int lane = tid & 31;
    const int warp = tid >> 5;
    const int wm = warp >> 2, wn = warp & 3;

    float acc[4][4][4];
#pragma unroll
    for (int mi = 0; mi < 4; mi++)
#pragma unroll
        for (int ni = 0; ni < 4; ni++)
#pragma unroll
            for (int f = 0; f < 4; f++) acc[mi][ni][f] = 0.f;

    constexpr int NCH = DD / 32;  // 32
    gemm_stage(As_s, Bs_s, 0, A, B, brow, bcol, 0, tid);
    gemm_stage(As_s, Bs_s, 1, A, B, brow, bcol, 32, tid);

    for (int i = 0; i < NCH; i++) {
        if (i + 1 < NCH) cp_wait<1>(); else cp_wait<0>();
        __syncthreads();
        if (i + 2 < NCH)
            gemm_stage(As_s, Bs_s, (i + 2) % 3, A, B, brow, bcol,
                       (i + 2) * 32, tid);
        gemm_compute(AsB + (i % 3) * AS_ELEM, BsB + (i % 3) * BS_ELEM,
                     lane, wm, wn, acc);
    }
    epi(acc, lane, wm, wn);
}

// ---------------------------------------------------------------------------
// K1: QKV GEMM + RoPE
// ---------------------------------------------------------------------------
__global__ __launch_bounds__(256, 2) void qkv_mma(
    const float* __restrict__ cosT, const float* __restrict__ sinT)
{
    extern __shared__ float sm[];
    const int mat = blockIdx.z;
    const float* __restrict__ w =
        (mat == 0) ? g_wqt : (mat == 1) ? g_wkt : g_wvt;
    float* __restrict__ out = (mat == 0) ? g_q : (mat == 1) ? g_k : g_v;
    const int brow = blockIdx.y * 128;
    const int bcol = blockIdx.x * 128;

    gemm_run(sm, g_xt, w, brow, bcol,
        [&](float acc[4][4][4], int lane, int wm, int wn) {
            const int ar = wm * 64 + (lane >> 2);
            const int ac = wn * 32 + (lane & 3) * 2;
#pragma unroll
            for (int mi = 0; mi < 4; mi++) {
#pragma unroll
                for (int hp = 0; hp < 2; hp++) {
                    const int row = brow + ar + mi * 16 + hp * 8;
                    const int bb = row >> 11;
                    const int ss = row & (SS - 1);
#pragma unroll
                    for (int ni = 0; ni < 4; ni++) {
                        const int col = bcol + ac + ni * 8;
                        const int hh = col >> 6;
                        const int dh = col & (DH - 1);
                        float c0 = acc[mi][ni][hp * 2 + 0];
                        float c1 = acc[mi][ni][hp * 2 + 1];
                        if (mat < 2) {
                            const int fi = ss * 32 + (dh >> 1);
                            const float cs = cosT[fi], sn = sinT[fi];
                            const float o0 = c0 * cs - c1 * sn;
                            const float o1 = c0 * sn + c1 * cs;
                            c0 = o0; c1 = o1;
                        }
                        if (mat == 0) { c0 *= 0.125f; c1 *= 0.125f; }
                        *reinterpret_cast<float2*>(
                            out + ((size_t)(bb * HH + hh) * SS + ss) * DH + dh) =
                            make_float2(__uint_as_float(f2tf(c0)),
                                        __uint_as_float(f2tf(c1)));
                    }
                }
            }
        });
}

// ---------------------------------------------------------------------------
// K3: output projection
// ---------------------------------------------------------------------------
__global__ __launch_bounds__(256, 2) void proj_mma(float* __restrict__ Cout)
{
    extern __shared__ float sm[];
    const int brow = blockIdx.y * 128;
    const int bcol = blockIdx.x * 128;

    gemm_run(sm, g_att, g_wot, brow, bcol,
        [&](float acc[4][4][4], int lane, int wm, int wn) {
            const int ar = wm * 64 + (lane >> 2);
            const int ac = wn * 32 + (lane & 3) * 2;
#pragma unroll
            for (int mi = 0; mi < 4; mi++)
#pragma unroll
                for (int hp = 0; hp < 2; hp++) {
                    const int row = brow + ar + mi * 16 + hp * 8;
#pragma unroll
                    for (int ni = 0; ni < 4; ni++) {
                        const int col = bcol + ac + ni * 8;
                        *reinterpret_cast<float2*>(
                            Cout + (size_t)row * DD + col) =
                            make_float2(acc[mi][ni][hp * 2],
                                        acc[mi][ni][hp * 2 + 1]);
                    }
                }
        });
}

// ---------------------------------------------------------------------------
// K2: flash attention. grid (S/256, H, B), block 512 (16 warps x m16n64).
// smem stride 72: Qs[256][72], Ks[2][64][72], Vs[2][64][72], Ps[256][72].
// ---------------------------------------------------------------------------
constexpr int AST = 72;
constexpr int QS_ELEM = 256 * AST;
constexpr int KS_ELEM = 64 * AST;
constexpr int ATT_SMEM = (2 * QS_ELEM + 4 * KS_ELEM) * (int)sizeof(float);

__device__ __forceinline__ void attn_stage_kv(
    uint32_t Ks_s, uint32_t Vs_s, int s,
    const float* __restrict__ K, const float* __restrict__ V,
    int kt, int tid)
{
    const float* Kp = K + (size_t)kt * 64 * DH;
    const float* Vp = V + (size_t)kt * 64 * DH;
#pragma unroll
    for (int i = 0; i < 2; i++) {
        int idx = tid + (i << 9);
        int r = idx >> 4, c4 = (idx & 15) << 2;
        cp16(Ks_s + (s * KS_ELEM + r * AST + c4) * 4, Kp + r * DH + c4);
        cp16(Vs_s + (s * KS_ELEM + r * AST + c4) * 4, Vp + r * DH + c4);
    }
    cp_commit();
}

__global__ __launch_bounds__(512, 1) void attn_mma()
{
    extern __shared__ float sm[];
    float* Qs = sm;                       // [256][72]
    float* Ks = Qs + QS_ELEM;             // [2][64][72]
    float* Vs = Ks + 2 * KS_ELEM;         // [2][64][72]
    float* Ps = Vs + 2 * KS_ELEM;         // [256][72]
    const uint32_t Qs_s = (uint32_t)__cvta_generic_to_shared(Qs);
    const uint32_t Ks_s = (uint32_t)__cvta_generic_to_shared(Ks);
    const uint32_t Vs_s = (uint32_t)__cvta_generic_to_shared(Vs);

    const int qt = blockIdx.x, h = blockIdx.y, b = blockIdx.z;
    const float* __restrict__ Q = g_q + ((size_t)(b * HH + h) * SS + qt * 256) * DH;
    const float* __restrict__ K = g_k + (size_t)(b * HH + h) * SS * DH;
    const float* __restrict__ V = g_v + (size_t)(b * HH + h) * SS * DH;

    const int tid = threadIdx.x;
    const int lane = tid & 31;
    const int warp = tid >> 5;   // 0..15

    // prologue: KV0 (grp0), Q (grp1), KV1 (grp2)
    attn_stage_kv(Ks_s, Vs_s, 0, K, V, 0, tid);
#pragma unroll
    for (int i = 0; i < 8; i++) {
        int idx = tid + (i << 9);
        int r = idx >> 4, c4 = (idx & 15) << 2;
        cp16(Qs_s + (r * AST + c4) * 4, Q + r * DH + c4);
    }
    cp_commit();
    attn_stage_kv(Ks_s, Vs_s, 1, K, V, 1, tid);

    float mrow[2] = {-1e30f, -1e30f};
    float lrow[2] = {0.f, 0.f};
    float o[8][4];
#pragma unroll
    for (int ni = 0; ni < 8; ni++)
#pragma unroll
        for (int f = 0; f < 4; f++) o[ni][f] = 0.f;

    const int rbase = warp * 16 + (lane >> 2);
    constexpr int NKT = SS / 64;  // 32

    for (int kt = 0; kt < NKT; kt++) {
        if (kt + 1 < NKT) cp_wait<1>(); else cp_wait<0>();
        __syncthreads();

        const int s = kt & 1;
        const float* Kb = Ks + s * KS_ELEM;
        const float* Vb = Vs + s * KS_ELEM;

        // S = Q @ K^T  (m16 x n64 x k64 per warp)
        float sacc[8][4];
#pragma unroll
        for (int ni = 0; ni < 8; ni++)
#pragma unroll
            for (int f = 0; f < 4; f++) sacc[ni][f] = 0.f;

#pragma unroll
        for (int ks = 0; ks < 8; ks++) {
            const int k0 = ks * 8;
            const float* ap = &Qs[rbase * AST + k0 + (lane & 3)];
            const uint32_t a0 = __float_as_uint(ap[0]);
            const uint32_t a1 = __float_as_uint(ap[8 * AST]);
            const uint32_t a2 = __float_as_uint(ap[4]);
            const uint32_t a3 = __float_as_uint(ap[8 * AST + 4]);
#pragma unroll
            for (int ni = 0; ni < 8; ni++) {
                const float* bp = &Kb[(ni * 8 + (lane >> 2)) * AST + k0 + (lane & 3)];
                mma8(sacc[ni], a0, a1, a2, a3,
                     __float_as_uint(bp[0]), __float_as_uint(bp[4]));
            }
        }

        // online softmax -> Ps (warp-private rows)
#pragma unroll
        for (int hp = 0; hp < 2; hp++) {
            float mx = -1e30f;
#pragma unroll
            for (int ni = 0; ni < 8; ni++)
                mx = fmaxf(mx, fmaxf(sacc[ni][hp * 2], sacc[ni][hp * 2 + 1]));
            mx = fmaxf(mx, __shfl_xor_sync(0xffffffffu, mx, 1));
            mx = fmaxf(mx, __shfl_xor_sync(0xffffffffu, mx, 2));
            const float mnew = fmaxf(mrow[hp], mx);
            const float corr = __expf(mrow[hp] - mnew);
            mrow[hp] = mnew;
            float rs = 0.f;
            const int prow = rbase + hp * 8;
#pragma unroll
            for (int ni = 0; ni < 8; ni++) {
                const float p0 = __expf(sacc[ni][hp * 2]     - mnew);
                const float p1 = __expf(sacc[ni][hp * 2 + 1] - mnew);
                rs += p0 + p1;
                *reinterpret_cast<float2*>(
                    &Ps[prow * AST + ni * 8 + (lane & 3) * 2]) =
                    make_float2(__uint_as_float(f2tf(p0)),
                                __uint_as_float(f2tf(p1)));
            }
            rs += __shfl_xor_sync(0xffffffffu, rs, 1);
            rs += __shfl_xor_sync(0xffffffffu, rs, 2);
            lrow[hp] = lrow[hp] * corr + rs;
#pragma unroll
            for (int ni = 0; ni < 8; ni++) {
                o[ni][hp * 2]     *= corr;
                o[ni][hp * 2 + 1] *= corr;
            }
        }
        __syncwarp();

        // O += P @ V
#pragma unroll
        for (int ks = 0; ks < 8; ks++) {
            const int k0 = ks * 8;
            const float* ap = &Ps[rbase * AST + k0 + (lane & 3)];
            const uint32_t a0 = __float_as_uint(ap[0]);
            const uint32_t a1 = __float_as_uint(ap[8 * AST]);
            const uint32_t a2 = __float_as_uint(ap[4]);
            const uint32_t a3 = __float_as_uint(ap[8 * AST + 4]);
#pragma unroll
            for (int ni = 0; ni < 8; ni++) {
                const float* bp = &Vb[(k0 + (lane & 3)) * AST + ni * 8 + (lane >> 2)];
                mma8(o[ni], a0, a1, a2, a3,
                     __float_as_uint(bp[0]), __float_as_uint(bp[4 * AST]));
            }
        }

        if (kt + 2 < NKT) {
            __syncthreads();   // all warps done reading slot s before refill
            attn_stage_kv(Ks_s, Vs_s, s, K, V, kt + 2, tid);
        }
    }

    // epilogue: normalize + round + write (b, s, h*64+dh)
#pragma unroll
    for (int hp = 0; hp < 2; hp++) {
        const float inv = 1.f / lrow[hp];
        const int row = qt * 256 + rbase + hp * 8;
#pragma unroll
        for (int ni = 0; ni < 8; ni++) {
            const int col = h * 64 + ni * 8 + (lane & 3) * 2;
            *reinterpret_cast<float2*>(
                g_att + (size_t)(b * SS + row) * DD + col) =
                make_float2(__uint_as_float(f2tf(o[ni][hp * 2] * inv)),
                            __uint_as_float(f2tf(o[ni][hp * 2 + 1] * inv)));
        }
    }
}

// ---------------------------------------------------------------------------
extern "C" void kernel_launch(void* const* d_in, const int* in_sizes, int n_in,
                              void* d_out, int out_size)
{
    const float* x    = (const float*)d_in[0];
    const float* cosT = (const float*)d_in[1];
    const float* sinT = (const float*)d_in[2];
    const float* wq   = (const float*)d_in[3];
    const float* wk   = (const float*)d_in[4];
    const float* wv   = (const float*)d_in[5];
    const float* wo   = (const float*)d_in[6];
    float* out = (float*)d_out;

    static bool attr_set = false;
    if (!attr_set) {
        cudaFuncSetAttribute(qkv_mma,
                             cudaFuncAttributeMaxDynamicSharedMemorySize, GEMM_SMEM);
        cudaFuncSetAttribute(proj_mma,
                             cudaFuncAttributeMaxDynamicSharedMemorySize, GEMM_SMEM);
        cudaFuncSetAttribute(attn_mma,
                             cudaFuncAttributeMaxDynamicSharedMemorySize, ATT_SMEM);
        attr_set = true;
    }

    cvt_inputs<<<dim3(512, 5), 256>>>(x, wq, wk, wv, wo);
    qkv_mma<<<dim3(DD / 128, MT / 128, 3), 256, GEMM_SMEM>>>(cosT, sinT);
    attn_mma<<<dim3(SS / 256, HH, BB), 512, ATT_SMEM>>>();
    proj_mma<<<dim3(DD / 128, MT / 128, 1), 256, GEMM_SMEM>>>(out);
}

// round 8
// speedup vs baseline: 1.1276x; 1.1276x over previous
#include <cuda_runtime.h>
#include <cstdint>

// ---------------------------------------------------------------------------
// MultiHeadAttention B=2,S=2048,D=1024,H=16,Dh=64 fp32 — R8:
//  * GEMMs: R6 shape (4 warps, 64x64/warp, 2 blk/SM) + ldmatrix fragments
//    (both operands K-major [row][36]; weights pre-transposed to [n][k])
//  * Attention: exactly R6 (8 warps m32n64, 256 thr, stride 72, 2-stage KV)
// ---------------------------------------------------------------------------

constexpr int BB = 2;
constexpr int SS = 2048;
constexpr int DD = 1024;
constexpr int HH = 16;
constexpr int DH = 64;
constexpr int MT = BB * SS;   // 4096

__device__ float g_q[BB * HH * SS * DH];
__device__ float g_k[BB * HH * SS * DH];
__device__ float g_v[BB * HH * SS * DH];
__device__ float g_att[MT * DD];
__device__ float g_xt[MT * DD];     // rna-rounded x
__device__ float g_wqt[DD * DD];    // rounded + transposed weights [n][k]
__device__ float g_wkt[DD * DD];
__device__ float g_wvt[DD * DD];
__device__ float g_wot[DD * DD];

__device__ __forceinline__ uint32_t f2tf(float x) {
    uint32_t r;
    asm("cvt.rna.tf32.f32 %0, %1;" : "=r"(r) : "f"(x));
    return r;
}
__device__ __forceinline__ void mma8(float* d, uint32_t a0, uint32_t a1,
                                     uint32_t a2, uint32_t a3,
                                     uint32_t b0, uint32_t b1) {
    asm volatile(
        "mma.sync.aligned.m16n8k8.row.col.f32.tf32.tf32.f32 "
        "{%0,%1,%2,%3}, {%4,%5,%6,%7}, {%8,%9}, {%0,%1,%2,%3};"
        : "+f"(d[0]), "+f"(d[1]), "+f"(d[2]), "+f"(d[3])
        : "r"(a0), "r"(a1), "r"(a2), "r"(a3), "r"(b0), "r"(b1));
}
__device__ __forceinline__ void ldsm4(uint32_t& r0, uint32_t& r1,
                                      uint32_t& r2, uint32_t& r3,
                                      uint32_t addr) {
    asm volatile(
        "ldmatrix.sync.aligned.m8n8.x4.shared.b16 {%0,%1,%2,%3}, [%4];"
        : "=r"(r0), "=r"(r1), "=r"(r2), "=r"(r3) : "r"(addr));
}
__device__ __forceinline__ void cp16(uint32_t dst, const void* src) {
    asm volatile("cp.async.cg.shared.global [%0], [%1], 16;"
                 :: "r"(dst), "l"(src));
}
__device__ __forceinline__ void cp_commit() {
    asm volatile("cp.async.commit_group;");
}
template <int N>
__device__ __forceinline__ void cp_wait() {
    asm volatile("cp.async.wait_group %0;" :: "n"(N));
}
__device__ __forceinline__ float4 cvt4(float4 v) {
    float4 o;
    o.x = __uint_as_float(f2tf(v.x));
    o.y = __uint_as_float(f2tf(v.y));
    o.z = __uint_as_float(f2tf(v.z));
    o.w = __uint_as_float(f2tf(v.w));
    return o;
}

// ---------------------------------------------------------------------------
// K0a: round x.  K0b: round + transpose weights -> [n][k].
// ---------------------------------------------------------------------------
__global__ __launch_bounds__(256) void cvt_x(const float* __restrict__ x) {
    const int n4 = (MT * DD) >> 2;
    const float4* s = reinterpret_cast<const float4*>(x);
    float4* d = reinterpret_cast<float4*>(g_xt);
    for (int i = blockIdx.x * 256 + threadIdx.x; i < n4; i += gridDim.x * 256)
        d[i] = cvt4(s[i]);
}

__global__ void cvt_wT(
    const float* __restrict__ wq, const float* __restrict__ wk,
    const float* __restrict__ wv, const float* __restrict__ wo) {
    __shared__ float t[32][33];
    const int z = blockIdx.z;
    const float* src = (z == 0) ? wq : (z == 1) ? wk : (z == 2) ? wv : wo;
    float* dst = (z == 0) ? g_wqt : (z == 1) ? g_wkt : (z == 2) ? g_wvt : g_wot;
    const int tx = threadIdx.x, ty = threadIdx.y;  // 32 x 8
    const int kb = blockIdx.y * 32, nb = blockIdx.x * 32;
#pragma unroll
    for (int i = 0; i < 4; i++) {
        int k = kb + ty + i * 8;
        t[ty + i * 8][tx] = __uint_as_float(f2tf(src[(size_t)k * DD + nb + tx]));
    }
    __syncthreads();
#pragma unroll
    for (int i = 0; i < 4; i++) {
        int n = nb + ty + i * 8;
        dst[(size_t)n * DD + kb + tx] = t[tx][ty + i * 8];
    }
}

// ---------------------------------------------------------------------------
// GEMM: 128x128 tile, BK=32, 4 warps (2x2), 64x64/warp, 3-stage cp.async.
// As [128][36] = A rows, Bs [128][36] = Bt rows (both K-major, ldmatrix CF).
// ---------------------------------------------------------------------------
constexpr int OP_ELEM = 128 * 36;   // 4608 floats per operand stage
constexpr int GEMM_SMEM = 3 * 2 * OP_ELEM * (int)sizeof(float);  // 110592

__device__ __forceinline__ void gemm_stage(
    uint32_t As_s, uint32_t Bs_s, int s, const float* __restrict__ A,
    const float* __restrict__ Bt, int brow, int bcol, int kk, int tid)
{
#pragma unroll
    for (int i = 0; i < 8; i++) {
        int idx = tid + (i << 7);
        int r = idx >> 3, c4 = (idx & 7) << 2;
        cp16(As_s + (s * OP_ELEM + r * 36 + c4) * 4,
             A + (size_t)(brow + r) * DD + kk + c4);
        cp16(Bs_s + (s * OP_ELEM + r * 36 + c4) * 4,
             Bt + (size_t)(bcol + r) * DD + kk + c4);
    }
    cp_commit();
}

// fragment loads via ldmatrix; per-lane address bases precomputed.
struct FragAddr {
    uint32_t a_base;  // As_s lane address for mi=0, ks=0 (within stage 0)
    uint32_t b_base;  // Bs_s lane address for nj=0, ks=0
};

__device__ __forceinline__ FragAddr frag_addr(
    uint32_t As_s, uint32_t Bs_s, int lane, int wm, int wn)
{
    // A: row = wm*64 + (l&7) + ((l>>3)&1)*8 (+16*mi), col = (l>>4)*4 (+8*ks)
    const int arow = wm * 64 + (lane & 7) + ((lane >> 3) & 1) * 8;
    const int acol = (lane >> 4) * 4;
    // B: row = wn*64 + (l&7) + (l>>4)*8 (+16*nj), col = ((l>>3)&1)*4 (+8*ks)
    const int brw = wn * 64 + (lane & 7) + (lane >> 4) * 8;
    const int bcl = ((lane >> 3) & 1) * 4;
    FragAddr f;
    f.a_base = As_s + (uint32_t)(arow * 36 + acol) * 4;
    f.b_base = Bs_s + (uint32_t)(brw * 36 + bcl) * 4;
    return f;
}

__device__ __forceinline__ void gemm_compute(
    const FragAddr& f, uint32_t stage_off, float acc[4][8][4])
{
#pragma unroll
    for (int ks = 0; ks < 4; ks++) {
        const uint32_t ko = stage_off + (uint32_t)(ks * 8) * 4;
        uint32_t a[4][4], b[8][2];
#pragma unroll
        for (int mi = 0; mi < 4; mi++)
            ldsm4(a[mi][0], a[mi][1], a[mi][2], a[mi][3],
                  f.a_base + ko + (uint32_t)(mi * 16 * 36) * 4);
#pragma unroll
        for (int nj = 0; nj < 4; nj++)
            ldsm4(b[2 * nj][0], b[2 * nj][1], b[2 * nj + 1][0],
                  b[2 * nj + 1][1],
                  f.b_base + ko + (uint32_t)(nj * 16 * 36) * 4);
#pragma unroll
        for (int mi = 0; mi < 4; mi++)
#pragma unroll
            for (int ni = 0; ni < 8; ni++)
                mma8(acc[mi][ni], a[mi][0], a[mi][1], a[mi][2], a[mi][3],
                     b[ni][0], b[ni][1]);
    }
}

template <typename EpiF>
__device__ __forceinline__ void gemm_run(
    float* sm, const float* __restrict__ A, const float* __restrict__ Bt,
    int brow, int bcol, EpiF epi)
{
    const uint32_t As_s = (uint32_t)__cvta_generic_to_shared(sm);
    const uint32_t Bs_s = (uint32_t)__cvta_generic_to_shared(sm + 3 * OP_ELEM);

    const int tid = threadIdx.x;
    const int lane = tid & 31;
    const int warp = tid >> 5;
    const int wm = warp >> 1, wn = warp & 1;
    const FragAddr f = frag_addr(As_s, Bs_s, lane, wm, wn);

    float acc[4][8][4];
#pragma unroll
    for (int mi = 0; mi < 4; mi++)
#pragma unroll
        for (int ni = 0; ni < 8; ni++)
#pragma unroll
            for (int fl = 0; fl < 4; fl++) acc[mi][ni][fl] = 0.f;

    constexpr int NCH = DD / 32;  // 32
    gemm_stage(As_s, Bs_s, 0, A, Bt, brow, bcol, 0, tid);
    gemm_stage(As_s, Bs_s, 1, A, Bt, brow, bcol, 32, tid);

    for (int i = 0; i < NCH; i++) {
        if (i + 1 < NCH) cp_wait<1>(); else cp_wait<0>();
        __syncthreads();
        if (i + 2 < NCH)
            gemm_stage(As_s, Bs_s, (i + 2) % 3, A, Bt, brow, bcol,
                       (i + 2) * 32, tid);
        gemm_compute(f, (uint32_t)((i % 3) * OP_ELEM) * 4, acc);
    }
    epi(acc, lane, wm, wn);
}

// ---------------------------------------------------------------------------
// K1: QKV GEMM + RoPE
// ---------------------------------------------------------------------------
__global__ __launch_bounds__(128, 2) void qkv_mma(
    const float* __restrict__ cosT, const float* __restrict__ sinT)
{
    extern __shared__ float sm[];
    const int mat = blockIdx.z;
    const float* __restrict__ w =
        (mat == 0) ? g_wqt : (mat == 1) ? g_wkt : g_wvt;
    float* __restrict__ out = (mat == 0) ? g_q : (mat == 1) ? g_k : g_v;
    const int brow = blockIdx.y * 128;
    const int bcol = blockIdx.x * 128;

    gemm_run(sm, g_xt, w, brow, bcol,
        [&](float acc[4][8][4], int lane, int wm, int wn) {
            const int ar = wm * 64 + (lane >> 2);
            const int ac = wn * 64 + (lane & 3) * 2;
#pragma unroll
            for (int mi = 0; mi < 4; mi++) {
#pragma unroll
                for (int hp = 0; hp < 2; hp++) {
                    const int row = brow + ar + mi * 16 + hp * 8;
                    const int bb = row >> 11;
                    const int ss = row & (SS - 1);
#pragma unroll
                    for (int ni = 0; ni < 8; ni++) {
                        const int col = bcol + ac + ni * 8;
                        const int hh = col >> 6;
                        const int dh = col & (DH - 1);
                        float c0 = acc[mi][ni][hp * 2 + 0];
                        float c1 = acc[mi][ni][hp * 2 + 1];
                        if (mat < 2) {
                            const int fi = ss * 32 + (dh >> 1);
                            const float cs = cosT[fi], sn = sinT[fi];
                            const float o0 = c0 * cs - c1 * sn;
                            const float o1 = c0 * sn + c1 * cs;
                            c0 = o0; c1 = o1;
                        }
                        if (mat == 0) { c0 *= 0.125f; c1 *= 0.125f; }
                        *reinterpret_cast<float2*>(
                            out + ((size_t)(bb * HH + hh) * SS + ss) * DH + dh) =
                            make_float2(__uint_as_float(f2tf(c0)),
                                        __uint_as_float(f2tf(c1)));
                    }
                }
            }
        });
}

// ---------------------------------------------------------------------------
// K3: output projection
// ---------------------------------------------------------------------------
__global__ __launch_bounds__(128, 2) void proj_mma(float* __restrict__ Cout)
{
    extern __shared__ float sm[];
    const int brow = blockIdx.y * 128;
    const int bcol = blockIdx.x * 128;

    gemm_run(sm, g_att, g_wot, brow, bcol,
        [&](float acc[4][8][4], int lane, int wm, int wn) {
            const int ar = wm * 64 + (lane >> 2);
            const int ac = wn * 64 + (lane & 3) * 2;
#pragma unroll
            for (int mi = 0; mi < 4; mi++)
#pragma unroll
                for (int hp = 0; hp < 2; hp++) {
                    const int row = brow + ar + mi * 16 + hp * 8;
#pragma unroll
                    for (int ni = 0; ni < 8; ni++) {
                        const int col = bcol + ac + ni * 8;
                        *reinterpret_cast<float2*>(
                            Cout + (size_t)row * DD + col) =
                            make_float2(acc[mi][ni][hp * 2],
                                        acc[mi][ni][hp * 2 + 1]);
                    }
                }
        });
}

// ---------------------------------------------------------------------------
// K2: flash attention — exactly R6 (best): 256 thr, 8 warps m32n64,
// stride 72, 2-stage KV ring.
// ---------------------------------------------------------------------------
constexpr int AST = 72;
constexpr int QS_ELEM = 256 * AST;
constexpr int KS_ELEM = 64 * AST;
constexpr int ATT_SMEM = (2 * QS_ELEM + 4 * KS_ELEM) * (int)sizeof(float);

__device__ __forceinline__ void attn_stage_kv(
    uint32_t Ks_s, uint32_t Vs_s, int s,
    const float* __restrict__ K, const float* __restrict__ V,
    int kt, int tid)
{
    const float* Kp = K + (size_t)kt * 64 * DH;
    const float* Vp = V + (size_t)kt * 64 * DH;
#pragma unroll
    for (int i = 0; i < 4; i++) {
        int idx = tid + (i << 8);
        int r = idx >> 4, c4 = (idx & 15) << 2;
        cp16(Ks_s + (s * KS_ELEM + r * AST + c4) * 4, Kp + r * DH + c4);
        cp16(Vs_s + (s * KS_ELEM + r * AST + c4) * 4, Vp + r * DH + c4);
    }
    cp_commit();
}

__global__ __launch_bounds__(256, 1) void attn_mma()
{
    extern __shared__ float sm[];
    float* Qs = sm;                       // [256][72]
    float* Ks = Qs + QS_ELEM;             // [2][64][72]
    float* Vs = Ks + 2 * KS_ELEM;         // [2][64][72]
    float* Ps = Vs + 2 * KS_ELEM;         // [256][72]
    const uint32_t Qs_s = (uint32_t)__cvta_generic_to_shared(Qs);
    const uint32_t Ks_s = (uint32_t)__cvta_generic_to_shared(Ks);
    const uint32_t Vs_s = (uint32_t)__cvta_generic_to_shared(Vs);

    const int qt = blockIdx.x, h = blockIdx.y, b = blockIdx.z;
    const float* __restrict__ Q = g_q + ((size_t)(b * HH + h) * SS + qt * 256) * DH;
    const float* __restrict__ K = g_k + (size_t)(b * HH + h) * SS * DH;
    const float* __restrict__ V = g_v + (size_t)(b * HH + h) * SS * DH;

    const int tid = threadIdx.x;
    const int lane = tid & 31;
    const int warp = tid >> 5;

    attn_stage_kv(Ks_s, Vs_s, 0, K, V, 0, tid);
#pragma unroll
    for (int i = 0; i < 16; i++) {
        int idx = tid + (i << 8);
        int r = idx >> 4, c4 = (idx & 15) << 2;
        cp16(Qs_s + (r * AST + c4) * 4, Q + r * DH + c4);
    }
    cp_commit();
    attn_stage_kv(Ks_s, Vs_s, 1, K, V, 1, tid);

    float mrow[2][2], lrow[2][2];
    float o[2][8][4];
#pragma unroll
    for (int mi = 0; mi < 2; mi++)
#pragma unroll
        for (int hp = 0; hp < 2; hp++) {
            mrow[mi][hp] = -1e30f;
            lrow[mi][hp] = 0.f;
        }
#pragma unroll
    for (int mi = 0; mi < 2; mi++)
#pragma unroll
        for (int ni = 0; ni < 8; ni++)
#pragma unroll
            for (int f = 0; f < 4; f++) o[mi][ni][f] = 0.f;

    const int rbase = warp * 32 + (lane >> 2);
    constexpr int NKT = SS / 64;  // 32

    for (int kt = 0; kt < NKT; kt++) {
        if (kt + 1 < NKT) cp_wait<1>(); else cp_wait<0>();
        __syncthreads();

        const int s = kt & 1;
        const float* Kb = Ks + s * KS_ELEM;
        const float* Vb = Vs + s * KS_ELEM;

        float sacc[2][8][4];
#pragma unroll
        for (int mi = 0; mi < 2; mi++)
#pragma unroll
            for (int ni = 0; ni < 8; ni++)
#pragma unroll
                for (int f = 0; f < 4; f++) sacc[mi][ni][f] = 0.f;

#pragma unroll
        for (int ks = 0; ks < 8; ks++) {
            const int k0 = ks * 8;
            uint32_t a[2][4];
#pragma unroll
            for (int mi = 0; mi < 2; mi++) {
                const float* ap = &Qs[(rbase + mi * 16) * AST + k0 + (lane & 3)];
                a[mi][0] = __float_as_uint(ap[0]);
                a[mi][1] = __float_as_uint(ap[8 * AST]);
                a[mi][2] = __float_as_uint(ap[4]);
                a[mi][3] = __float_as_uint(ap[8 * AST + 4]);
            }
#pragma unroll
            for (int ni = 0; ni < 8; ni++) {
                const float* bp = &Kb[(ni * 8 + (lane >> 2)) * AST + k0 + (lane & 3)];
                const uint32_t b0 = __float_as_uint(bp[0]);
                const uint32_t b1 = __float_as_uint(bp[4]);
#pragma unroll
                for (int mi = 0; mi < 2; mi++)
                    mma8(sacc[mi][ni], a[mi][0], a[mi][1], a[mi][2], a[mi][3],
                         b0, b1);
            }
        }

#pragma unroll
        for (int mi = 0; mi < 2; mi++) {
#pragma unroll
            for (int hp = 0; hp < 2; hp++) {
                float mx = -1e30f;
#pragma unroll
                for (int ni = 0; ni < 8; ni++)
                    mx = fmaxf(mx, fmaxf(sacc[mi][ni][hp * 2],
                                         sacc[mi][ni][hp * 2 + 1]));
                mx = fmaxf(mx, __shfl_xor_sync(0xffffffffu, mx, 1));
                mx = fmaxf(mx, __shfl_xor_sync(0xffffffffu, mx, 2));
                const float mnew = fmaxf(mrow[mi][hp], mx);
                const float corr = __expf(mrow[mi][hp] - mnew);
                mrow[mi][hp] = mnew;
                float rs = 0.f;
                const int prow = rbase + mi * 16 + hp * 8;
#pragma unroll
                for (int ni = 0; ni < 8; ni++) {
                    const float p0 = __expf(sacc[mi][ni][hp * 2]     - mnew);
                    const float p1 = __expf(sacc[mi][ni][hp * 2 + 1] - mnew);
                    rs += p0 + p1;
                    *reinterpret_cast<float2*>(
                        &Ps[prow * AST + ni * 8 + (lane & 3) * 2]) =
                        make_float2(__uint_as_float(f2tf(p0)),
                                    __uint_as_float(f2tf(p1)));
                }
                rs += __shfl_xor_sync(0xffffffffu, rs, 1);
                rs += __shfl_xor_sync(0xffffffffu, rs, 2);
                lrow[mi][hp] = lrow[mi][hp] * corr + rs;
#pragma unroll
                for (int ni = 0; ni < 8; ni++) {
                    o[mi][ni][hp * 2]     *= corr;
                    o[mi][ni][hp * 2 + 1] *= corr;
                }
            }
        }
        __syncwarp();

#pragma unroll
        for (int ks = 0; ks < 8; ks++) {
            const int k0 = ks * 8;
            uint32_t a[2][4];
#pragma unroll
            for (int mi = 0; mi < 2; mi++) {
                const float* ap = &Ps[(rbase + mi * 16) * AST + k0 + (lane & 3)];
                a[mi][0] = __float_as_uint(ap[0]);
                a[mi][1] = __float_as_uint(ap[8 * AST]);
                a[mi][2] = __float_as_uint(ap[4]);
                a[mi][3] = __float_as_uint(ap[8 * AST + 4]);
            }
#pragma unroll
            for (int ni = 0; ni < 8; ni++) {
                const float* bp = &Vb[(k0 + (lane & 3)) * AST + ni * 8 + (lane >> 2)];
                const uint32_t b0 = __float_as_uint(bp[0]);
                const uint32_t b1 = __float_as_uint(bp[4 * AST]);
#pragma unroll
                for (int mi = 0; mi < 2; mi++)
                    mma8(o[mi][ni], a[mi][0], a[mi][1], a[mi][2], a[mi][3],
                         b0, b1);
            }
        }

        if (kt + 2 < NKT) {
            __syncthreads();
            attn_stage_kv(Ks_s, Vs_s, s, K, V, kt + 2, tid);
        }
    }

#pragma unroll
    for (int mi = 0; mi < 2; mi++)
#pragma unroll
        for (int hp = 0; hp < 2; hp++) {
            const float inv = 1.f / lrow[mi][hp];
            const int row = qt * 256 + rbase + mi * 16 + hp * 8;
#pragma unroll
            for (int ni = 0; ni < 8; ni++) {
                const int col = h * 64 + ni * 8 + (lane & 3) * 2;
                *reinterpret_cast<float2*>(
                    g_att + (size_t)(b * SS + row) * DD + col) =
                    make_float2(
                        __uint_as_float(f2tf(o[mi][ni][hp * 2] * inv)),
                        __uint_as_float(f2tf(o[mi][ni][hp * 2 + 1] * inv)));
            }
        }
}

// ---------------------------------------------------------------------------
extern "C" void kernel_launch(void* const* d_in, const int* in_sizes, int n_in,
                              void* d_out, int out_size)
{
    const float* x    = (const float*)d_in[0];
    const float* cosT = (const float*)d_in[1];
    const float* sinT = (const float*)d_in[2];
    const float* wq   = (const float*)d_in[3];
    const float* wk   = (const float*)d_in[4];
    const float* wv   = (const float*)d_in[5];
    const float* wo   = (const float*)d_in[6];
    float* out = (float*)d_out;

    static bool attr_set = false;
    if (!attr_set) {
        cudaFuncSetAttribute(qkv_mma,
                             cudaFuncAttributeMaxDynamicSharedMemorySize, GEMM_SMEM);
        cudaFuncSetAttribute(proj_mma,
                             cudaFuncAttributeMaxDynamicSharedMemorySize, GEMM_SMEM);
        cudaFuncSetAttribute(attn_mma,
                             cudaFuncAttributeMaxDynamicSharedMemorySize, ATT_SMEM);
        attr_set = true;
    }

    cvt_x<<<256, 256>>>(x);
    cvt_wT<<<dim3(32, 32, 4), dim3(32, 8)>>>(wq, wk, wv, wo);
    qkv_mma<<<dim3(DD / 128, MT / 128, 3), 128, GEMM_SMEM>>>(cosT, sinT);
    attn_mma<<<dim3(SS / 256, HH, BB), 256, ATT_SMEM>>>();
    proj_mma<<<dim3(DD / 128, MT / 128, 1), 128, GEMM_SMEM>>>(out);
}

// round 9
// speedup vs baseline: 1.2061x; 1.0696x over previous
#include <cuda_runtime.h>
#include <cstdint>

// ---------------------------------------------------------------------------
// MultiHeadAttention B=2,S=2048,D=1024,H=16,Dh=64 fp32 — R9:
//  * GEMMs: R6 config (4 warps, 64x64/warp, As[128][36]/Bs[32][136], 2 blk/SM)
//  * V stored transposed [b,h,dh,s] (smem-transpose epilogue in qkv)
//  * Attention: ldmatrix for Q/K/P/V fragments (chunked stride-36 layouts)
// ---------------------------------------------------------------------------

constexpr int BB = 2;
constexpr int SS = 2048;
constexpr int DD = 1024;
constexpr int HH = 16;
constexpr int DH = 64;
constexpr int MT = BB * SS;   // 4096

__device__ float g_q[BB * HH * SS * DH];
__device__ float g_k[BB * HH * SS * DH];
__device__ float g_vt[BB * HH * DH * SS];   // V transposed: [b,h,dh,s]
__device__ float g_att[MT * DD];
__device__ float g_xt[MT * DD];
__device__ float g_wqt[DD * DD];
__device__ float g_wkt[DD * DD];
__device__ float g_wvt[DD * DD];
__device__ float g_wot[DD * DD];

__device__ __forceinline__ uint32_t f2tf(float x) {
    uint32_t r;
    asm("cvt.rna.tf32.f32 %0, %1;" : "=r"(r) : "f"(x));
    return r;
}
__device__ __forceinline__ void mma8(float* d, uint32_t a0, uint32_t a1,
                                     uint32_t a2, uint32_t a3,
                                     uint32_t b0, uint32_t b1) {
    asm volatile(
        "mma.sync.aligned.m16n8k8.row.col.f32.tf32.tf32.f32 "
        "{%0,%1,%2,%3}, {%4,%5,%6,%7}, {%8,%9}, {%0,%1,%2,%3};"
        : "+f"(d[0]), "+f"(d[1]), "+f"(d[2]), "+f"(d[3])
        : "r"(a0), "r"(a1), "r"(a2), "r"(a3), "r"(b0), "r"(b1));
}
__device__ __forceinline__ void ldsm4(uint32_t& r0, uint32_t& r1,
                                      uint32_t& r2, uint32_t& r3,
                                      uint32_t addr) {
    asm volatile(
        "ldmatrix.sync.aligned.m8n8.x4.shared.b16 {%0,%1,%2,%3}, [%4];"
        : "=r"(r0), "=r"(r1), "=r"(r2), "=r"(r3) : "r"(addr));
}
__device__ __forceinline__ void cp16(uint32_t dst, const void* src) {
    asm volatile("cp.async.cg.shared.global [%0], [%1], 16;"
                 :: "r"(dst), "l"(src));
}
__device__ __forceinline__ void cp_commit() {
    asm volatile("cp.async.commit_group;");
}
template <int N>
__device__ __forceinline__ void cp_wait() {
    asm volatile("cp.async.wait_group %0;" :: "n"(N));
}
__device__ __forceinline__ float4 cvt4(float4 v) {
    float4 o;
    o.x = __uint_as_float(f2tf(v.x));
    o.y = __uint_as_float(f2tf(v.y));
    o.z = __uint_as_float(f2tf(v.z));
    o.w = __uint_as_float(f2tf(v.w));
    return o;
}

// ---------------------------------------------------------------------------
// K0: pre-round x, wq, wk, wv, wo (no transpose; R6 layout).
// ---------------------------------------------------------------------------
__global__ __launch_bounds__(256) void cvt_inputs(
    const float* __restrict__ x,
    const float* __restrict__ wq, const float* __restrict__ wk,
    const float* __restrict__ wv, const float* __restrict__ wo)
{
    const int z = blockIdx.y;
    const float* src = (z == 0) ? x : (z == 1) ? wq : (z == 2) ? wk
                       : (z == 3) ? wv : wo;
    float* dst = (z == 0) ? g_xt : (z == 1) ? g_wqt : (z == 2) ? g_wkt
                 : (z == 3) ? g_wvt : g_wot;
    const int n4 = ((z == 0) ? MT * DD : DD * DD) >> 2;
    const float4* s4 = reinterpret_cast<const float4*>(src);
    float4* d4 = reinterpret_cast<float4*>(dst);
    for (int i = blockIdx.x * blockDim.x + threadIdx.x; i < n4;
         i += gridDim.x * blockDim.x)
        d4[i] = cvt4(s4[i]);
}

// ---------------------------------------------------------------------------
// GEMM (R6): 128x128 tile, BK=32, 4 warps (2x2), 64x64/warp, 3-stage cp.async.
// As [128][36], Bs [32][136].
// ---------------------------------------------------------------------------
constexpr int AS_ELEM = 128 * 36;   // 4608
constexpr int BS_ELEM = 32 * 136;   // 4352
constexpr int GEMM_SMEM = 3 * (AS_ELEM + BS_ELEM) * (int)sizeof(float); // 107520

__device__ __forceinline__ void gemm_stage(
    uint32_t As_s, uint32_t Bs_s, int s, const float* __restrict__ A,
    const float* __restrict__ B, int brow, int bcol, int kk, int tid)
{
#pragma unroll
    for (int i = 0; i < 8; i++) {
        int idx = tid + (i << 7);
        int r = idx >> 3, c4 = (idx & 7) << 2;
        cp16(As_s + (s * AS_ELEM + r * 36 + c4) * 4,
             A + (size_t)(brow + r) * DD + kk + c4);
    }
#pragma unroll
    for (int i = 0; i < 8; i++) {
        int idx = tid + (i << 7);
        int r = idx >> 5, c4 = (idx & 31) << 2;
        cp16(Bs_s + (s * BS_ELEM + r * 136 + c4) * 4,
             B + (size_t)(kk + r) * DD + bcol + c4);
    }
    cp_commit();
}

__device__ __forceinline__ void gemm_compute(
    const float* As, const float* Bs, int lane, int wm, int wn,
    float acc[4][8][4])
{
    const int ar = wm * 64 + (lane >> 2);
    const int bc = wn * 64 + (lane >> 2);
#pragma unroll
    for (int ks = 0; ks < 4; ks++) {
        const int k0 = ks * 8;
        uint32_t a[4][4], b[8][2];
        const int acl = k0 + (lane & 3);
#pragma unroll
        for (int mi = 0; mi < 4; mi++) {
            const float* p = &As[(ar + mi * 16) * 36 + acl];
            a[mi][0] = __float_as_uint(p[0]);
            a[mi][2] = __float_as_uint(p[4]);
            a[mi][1] = __float_as_uint(p[8 * 36]);
            a[mi][3] = __float_as_uint(p[8 * 36 + 4]);
        }
        const int br = k0 + (lane & 3);
#pragma unroll
        for (int ni = 0; ni < 8; ni++) {
            const float* p = &Bs[br * 136 + bc + ni * 8];
            b[ni][0] = __float_as_uint(p[0]);
            b[ni][1] = __float_as_uint(p[4 * 136]);
        }
#pragma unroll
        for (int mi = 0; mi < 4; mi++)
#pragma unroll
            for (int ni = 0; ni < 8; ni++)
                mma8(acc[mi][ni], a[mi][0], a[mi][1], a[mi][2], a[mi][3],
                     b[ni][0], b[ni][1]);
    }
}

template <typename EpiF>
__device__ __forceinline__ void gemm_run(
    float* sm, const float* __restrict__ A, const float* __restrict__ B,
    int brow, int bcol, EpiF epi)
{
    const uint32_t As_s = (uint32_t)__cvta_generic_to_shared(sm);
    const uint32_t Bs_s = (uint32_t)__cvta_generic_to_shared(sm + 3 * AS_ELEM);
    const float* AsB = sm;
    const float* BsB = sm + 3 * AS_ELEM;

    const int tid = threadIdx.x;
    const int lane = tid & 31;
    const int warp = tid >> 5;
    const int wm = warp >> 1, wn = warp & 1;

    float acc[4][8][4];
#pragma unroll
    for (int mi = 0; mi < 4; mi++)
#pragma unroll
        for (int ni = 0; ni < 8; ni++)
#pragma unroll
            for (int f = 0; f < 4; f++) acc[mi][ni][f] = 0.f;

    constexpr int NCH = DD / 32;  // 32
    gemm_stage(As_s, Bs_s, 0, A, B, brow, bcol, 0, tid);
    gemm_stage(As_s, Bs_s, 1, A, B, brow, bcol, 32, tid);

    for (int i = 0; i < NCH; i++) {
        if (i + 1 < NCH) cp_wait<1>(); else cp_wait<0>();
        __syncthreads();
        if (i + 2 < NCH)
            gemm_stage(As_s, Bs_s, (i + 2) % 3, A, B, brow, bcol,
                       (i + 2) * 32, tid);
        gemm_compute(AsB + (i % 3) * AS_ELEM, BsB + (i % 3) * BS_ELEM,
                     lane, wm, wn, acc);
    }
    epi(acc, lane, wm, wn);
}

// ---------------------------------------------------------------------------
// K1: QKV GEMM + RoPE.  mat==2 (V): smem transpose -> g_vt[b,h,dh,s].
// ---------------------------------------------------------------------------
__global__ __launch_bounds__(128, 2) void qkv_mma(
    const float* __restrict__ cosT, const float* __restrict__ sinT)
{
    extern __shared__ float sm[];
    const int mat = blockIdx.z;
    const float* __restrict__ w =
        (mat == 0) ? g_wqt : (mat == 1) ? g_wkt : g_wvt;
    const int brow = blockIdx.y * 128;
    const int bcol = blockIdx.x * 128;

    gemm_run(sm, g_xt, w, brow, bcol,
        [&](float acc[4][8][4], int lane, int wm, int wn) {
            const int tid = threadIdx.x;
            if (mat < 2) {
                float* __restrict__ out = (mat == 0) ? g_q : g_k;
                const int ar = wm * 64 + (lane >> 2);
                const int ac = wn * 64 + (lane & 3) * 2;
#pragma unroll
                for (int mi = 0; mi < 4; mi++) {
#pragma unroll
                    for (int hp = 0; hp < 2; hp++) {
                        const int row = brow + ar + mi * 16 + hp * 8;
                        const int bb = row >> 11;
                        const int ss = row & (SS - 1);
#pragma unroll
                        for (int ni = 0; ni < 8; ni++) {
                            const int col = bcol + ac + ni * 8;
                            const int hh = col >> 6;
                            const int dh = col & (DH - 1);
                            float c0 = acc[mi][ni][hp * 2 + 0];
                            float c1 = acc[mi][ni][hp * 2 + 1];
                            const int fi = ss * 32 + (dh >> 1);
                            const float cs = cosT[fi], sn = sinT[fi];
                            const float o0 = c0 * cs - c1 * sn;
                            const float o1 = c0 * sn + c1 * cs;
                            c0 = o0; c1 = o1;
                            if (mat == 0) { c0 *= 0.125f; c1 *= 0.125f; }
                            *reinterpret_cast<float2*>(
                                out + ((size_t)(bb * HH + hh) * SS + ss) * DH + dh) =
                                make_float2(__uint_as_float(f2tf(c0)),
                                            __uint_as_float(f2tf(c1)));
                        }
                    }
                }
            } else {
                // V: transpose via smem (reuse stage buffers), store [dh][s]
                __syncthreads();  // all warps done with stage buffers
                float* T = sm;    // [128 cols][132] transposed tile
                const int ar = wm * 64 + (lane >> 2);
                const int ac = wn * 64 + (lane & 3) * 2;
#pragma unroll
                for (int mi = 0; mi < 4; mi++)
#pragma unroll
                    for (int hp = 0; hp < 2; hp++) {
                        const int rl = ar + mi * 16 + hp * 8;
#pragma unroll
                        for (int ni = 0; ni < 8; ni++) {
                            const int cl = ac + ni * 8;
                            T[(cl)     * 132 + rl] =
                                __uint_as_float(f2tf(acc[mi][ni][hp * 2]));
                            T[(cl + 1) * 132 + rl] =
                                __uint_as_float(f2tf(acc[mi][ni][hp * 2 + 1]));
                        }
                    }
                __syncthreads();
                const int bb = brow >> 11;
                const int srow = brow & (SS - 1);
#pragma unroll
                for (int i = 0; i < 32; i++) {
                    int idx = tid + (i << 7);
                    int r = idx >> 5, c4 = (idx & 31) << 2;
                    const int dhg = bcol + r;
                    const int hh = dhg >> 6, dh = dhg & 63;
                    float4 v = *reinterpret_cast<float4*>(&T[r * 132 + c4]);
                    *reinterpret_cast<float4*>(
                        g_vt + ((size_t)(bb * HH + hh) * DH + dh) * SS +
                        srow + c4) = v;
                }
            }
        });
}

// ---------------------------------------------------------------------------
// K3: output projection (R6)
// ---------------------------------------------------------------------------
__global__ __launch_bounds__(128, 2) void proj_mma(float* __restrict__ Cout)
{
    extern __shared__ float sm[];
    const int brow = blockIdx.y * 128;
    const int bcol = blockIdx.x * 128;

    gemm_run(sm, g_att, g_wot, brow, bcol,
        [&](float acc[4][8][4], int lane, int wm, int wn) {
            const int ar = wm * 64 + (lane >> 2);
            const int ac = wn * 64 + (lane & 3) * 2;
#pragma unroll
            for (int mi = 0; mi < 4; mi++)
#pragma unroll
                for (int hp = 0; hp < 2; hp++) {
                    const int row = brow + ar + mi * 16 + hp * 8;
#pragma unroll
                    for (int ni = 0; ni < 8; ni++) {
                        const int col = bcol + ac + ni * 8;
                        *reinterpret_cast<float2*>(
                            Cout + (size_t)row * DD + col) =
                            make_float2(acc[mi][ni][hp * 2],
                                        acc[mi][ni][hp * 2 + 1]);
                    }
                }
        });
}

// ---------------------------------------------------------------------------
// K2: flash attention with ldmatrix fragments.
// grid (S/256, H, B), block 256 (8 warps x m32n64).
// Layouts (chunked, stride 36 floats = 144 B, ldmatrix conflict-free):
//   Qs[2][256][36]  (chunk = dh>>5)         18432 fl
//   Ks[2 stage][2 chunk][64][36]             9216 fl
//   Vs[2 stage][2 chunk][64][36]  (V^T: rows=dh, cols=s)
//   Ps[2][256][36]  (chunk = s>>5)          18432 fl
// ---------------------------------------------------------------------------
constexpr int ATT_SMEM = (18432 + 9216 + 9216 + 18432) * (int)sizeof(float);

__device__ __forceinline__ void attn_stage_kv(
    uint32_t Ks_s, uint32_t Vs_s, int s,
    const float* __restrict__ K, const float* __restrict__ Vt,
    int kt, int tid)
{
#pragma unroll
    for (int i = 0; i < 4; i++) {
        int idx = tid + (i << 8);
        int r = idx >> 4, c4 = (idx & 15) << 2;
        const uint32_t doff =
            (uint32_t)(s * 4608 + (c4 >> 5) * 2304 + r * 36 + (c4 & 31)) * 4;
        cp16(Ks_s + doff, K + (size_t)(kt * 64 + r) * DH + c4);
        cp16(Vs_s + doff, Vt + (size_t)r * SS + kt * 64 + c4);
    }
    cp_commit();
}

__global__ __launch_bounds__(256, 1) void attn_mma()
{
    extern __shared__ float sm[];
    float* Qs = sm;               // 18432
    float* Ks = Qs + 18432;       // 9216
    float* Vs = Ks + 9216;        // 9216
    float* Ps = Vs + 9216;        // 18432
    const uint32_t Qs_s = (uint32_t)__cvta_generic_to_shared(Qs);
    const uint32_t Ks_s = (uint32_t)__cvta_generic_to_shared(Ks);
    const uint32_t Vs_s = (uint32_t)__cvta_generic_to_shared(Vs);
    const uint32_t Ps_s = (uint32_t)__cvta_generic_to_shared(Ps);

    const int qt = blockIdx.x, h = blockIdx.y, b = blockIdx.z;
    const float* __restrict__ Q  = g_q  + ((size_t)(b * HH + h) * SS + qt * 256) * DH;
    const float* __restrict__ K  = g_k  + (size_t)(b * HH + h) * SS * DH;
    const float* __restrict__ Vt = g_vt + (size_t)(b * HH + h) * DH * SS;

    const int tid = threadIdx.x;
    const int lane = tid & 31;
    const int warp = tid >> 5;
    const int qbase = warp * 32;

    // prologue: KV0, Q, KV1
    attn_stage_kv(Ks_s, Vs_s, 0, K, Vt, 0, tid);
#pragma unroll
    for (int i = 0; i < 16; i++) {
        int idx = tid + (i << 8);
        int r = idx >> 4, c4 = (idx & 15) << 2;
        cp16(Qs_s + (uint32_t)((c4 >> 5) * 9216 + r * 36 + (c4 & 31)) * 4,
             Q + (size_t)r * DH + c4);
    }
    cp_commit();
    attn_stage_kv(Ks_s, Vs_s, 1, K, Vt, 1, tid);

    // ldmatrix lane address bases (bytes)
    const int arow = (lane & 7) + ((lane >> 3) & 1) * 8;
    const int acol = (lane >> 4) * 4;
    const int brow = (lane & 7) + (lane >> 4) * 8;
    const int bcl  = ((lane >> 3) & 1) * 4;
    const uint32_t qa = Qs_s + (uint32_t)((qbase + arow) * 36 + acol) * 4;
    const uint32_t pa = Ps_s + (uint32_t)((qbase + arow) * 36 + acol) * 4;
    const uint32_t kb = Ks_s + (uint32_t)(brow * 36 + bcl) * 4;
    const uint32_t vb = Vs_s + (uint32_t)(brow * 36 + bcl) * 4;

    float mrow[2][2], lrow[2][2];
    float o[2][8][4];
#pragma unroll
    for (int mi = 0; mi < 2; mi++)
#pragma unroll
        for (int hp = 0; hp < 2; hp++) { mrow[mi][hp] = -1e30f; lrow[mi][hp] = 0.f; }
#pragma unroll
    for (int mi = 0; mi < 2; mi++)
#pragma unroll
        for (int ni = 0; ni < 8; ni++)
#pragma unroll
            for (int f = 0; f < 4; f++) o[mi][ni][f] = 0.f;

    constexpr int NKT = SS / 64;  // 32

    for (int kt = 0; kt < NKT; kt++) {
        if (kt + 1 < NKT) cp_wait<1>(); else cp_wait<0>();
        __syncthreads();

        const int s = kt & 1;
        const uint32_t sOff = (uint32_t)(s * 4608) * 4;

        // ---- S = Q @ K^T (m32 n64 k64 per warp), ldmatrix fragments ----
        float sacc[2][8][4];
#pragma unroll
        for (int mi = 0; mi < 2; mi++)
#pragma unroll
            for (int ni = 0; ni < 8; ni++)
#pragma unroll
                for (int f = 0; f < 4; f++) sacc[mi][ni][f] = 0.f;

#pragma unroll
        for (int ks = 0; ks < 8; ks++) {
            const uint32_t koA = (uint32_t)((ks >> 2) * 36864 + (ks & 3) * 32);
            const uint32_t koB = (uint32_t)((ks >> 2) * 9216  + (ks & 3) * 32);
            uint32_t a[2][4], bf[8][2];
#pragma unroll
            for (int mi = 0; mi < 2; mi++)
                ldsm4(a[mi][0], a[mi][1], a[mi][2], a[mi][3],
                      qa + koA + (uint32_t)(mi * 2304));
#pragma unroll
            for (int nj = 0; nj < 4; nj++)
                ldsm4(bf[2 * nj][0], bf[2 * nj][1],
                      bf[2 * nj + 1][0], bf[2 * nj + 1][1],
                      kb + sOff + koB + (uint32_t)(nj * 2304));
#pragma unroll
            for (int mi = 0; mi < 2; mi++)
#pragma unroll
                for (int ni = 0; ni < 8; ni++)
                    mma8(sacc[mi][ni], a[mi][0], a[mi][1], a[mi][2], a[mi][3],
                         bf[ni][0], bf[ni][1]);
        }

        // ---- online softmax -> Ps (chunked layout) ----
#pragma unroll
        for (int mi = 0; mi < 2; mi++) {
#pragma unroll
            for (int hp = 0; hp < 2; hp++) {
                float mx = -1e30f;
#pragma unroll
                for (int ni = 0; ni < 8; ni++)
                    mx = fmaxf(mx, fmaxf(sacc[mi][ni][hp * 2],
                                         sacc[mi][ni][hp * 2 + 1]));
                mx = fmaxf(mx, __shfl_xor_sync(0xffffffffu, mx, 1));
                mx = fmaxf(mx, __shfl_xor_sync(0xffffffffu, mx, 2));
                const float mnew = fmaxf(mrow[mi][hp], mx);
                const float corr = __expf(mrow[mi][hp] - mnew);
                mrow[mi][hp] = mnew;
                float rs = 0.f;
                const int prow = qbase + mi * 16 + hp * 8 + (lane >> 2);
#pragma unroll
                for (int ni = 0; ni < 8; ni++) {
                    const float p0 = __expf(sacc[mi][ni][hp * 2]     - mnew);
                    const float p1 = __expf(sacc[mi][ni][hp * 2 + 1] - mnew);
                    rs += p0 + p1;
                    const int local = (ni & 3) * 8 + 2 * (lane & 3);
                    *reinterpret_cast<float2*>(
                        &Ps[(ni >> 2) * 9216 + prow * 36 + local]) =
                        make_float2(__uint_as_float(f2tf(p0)),
                                    __uint_as_float(f2tf(p1)));
                }
                rs += __shfl_xor_sync(0xffffffffu, rs, 1);
                rs += __shfl_xor_sync(0xffffffffu, rs, 2);
                lrow[mi][hp] = lrow[mi][hp] * corr + rs;
#pragma unroll
                for (int ni = 0; ni < 8; ni++) {
                    o[mi][ni][hp * 2]     *= corr;
                    o[mi][ni][hp * 2 + 1] *= corr;
                }
            }
        }
        __syncwarp();

        // ---- O += P @ V (A=P via ldsm, B=V^T via ldsm) ----
#pragma unroll
        for (int ks = 0; ks < 8; ks++) {
            const uint32_t koA = (uint32_t)((ks >> 2) * 36864 + (ks & 3) * 32);
            const uint32_t koB = (uint32_t)((ks >> 2) * 9216  + (ks & 3) * 32);
            uint32_t a[2][4], bf[8][2];
#pragma unroll
            for (int mi = 0; mi < 2; mi++)
                ldsm4(a[mi][0], a[mi][1], a[mi][2], a[mi][3],
                      pa + koA + (uint32_t)(mi * 2304));
#pragma unroll
            for (int nj = 0; nj < 4; nj++)
                ldsm4(bf[2 * nj][0], bf[2 * nj][1],
                      bf[2 * nj + 1][0], bf[2 * nj + 1][1],
                      vb + sOff + koB + (uint32_t)(nj * 2304));
#pragma unroll
            for (int mi = 0; mi < 2; mi++)
#pragma unroll
                for (int ni = 0; ni < 8; ni++)
                    mma8(o[mi][ni], a[mi][0], a[mi][1], a[mi][2], a[mi][3],
                         bf[ni][0], bf[ni][1]);
        }

        if (kt + 2 < NKT) {
            __syncthreads();
            attn_stage_kv(Ks_s, Vs_s, s, K, Vt, kt + 2, tid);
        }
    }

    // epilogue: normalize + round + write (b, s, h*64+dh)
#pragma unroll
    for (int mi = 0; mi < 2; mi++)
#pragma unroll
        for (int hp = 0; hp < 2; hp++) {
            const float inv = 1.f / lrow[mi][hp];
            const int row = qt * 256 + qbase + mi * 16 + hp * 8 + (lane >> 2);
#pragma unroll
            for (int ni = 0; ni < 8; ni++) {
                const int col = h * 64 + ni * 8 + (lane & 3) * 2;
                *reinterpret_cast<float2*>(
                    g_att + (size_t)(b * SS + row) * DD + col) =
                    make_float2(
                        __uint_as_float(f2tf(o[mi][ni][hp * 2] * inv)),
                        __uint_as_float(f2tf(o[mi][ni][hp * 2 + 1] * inv)));
            }
        }
}

// ---------------------------------------------------------------------------
extern "C" void kernel_launch(void* const* d_in, const int* in_sizes, int n_in,
                              void* d_out, int out_size)
{
    const float* x    = (const float*)d_in[0];
    const float* cosT = (const float*)d_in[1];
    const float* sinT = (const float*)d_in[2];
    const float* wq   = (const float*)d_in[3];
    const float* wk   = (const float*)d_in[4];
    const float* wv   = (const float*)d_in[5];
    const float* wo   = (const float*)d_in[6];
    float* out = (float*)d_out;

    static bool attr_set = false;
    if (!attr_set) {
        cudaFuncSetAttribute(qkv_mma,
                             cudaFuncAttributeMaxDynamicSharedMemorySize, GEMM_SMEM);
        cudaFuncSetAttribute(proj_mma,
                             cudaFuncAttributeMaxDynamicSharedMemorySize, GEMM_SMEM);
        cudaFuncSetAttribute(attn_mma,
                             cudaFuncAttributeMaxDynamicSharedMemorySize, ATT_SMEM);
        attr_set = true;
    }

    cvt_inputs<<<dim3(512, 5), 256>>>(x, wq, wk, wv, wo);
    qkv_mma<<<dim3(DD / 128, MT / 128, 3), 128, GEMM_SMEM>>>(cosT, sinT);
    attn_mma<<<dim3(SS / 256, HH, BB), 256, ATT_SMEM>>>();
    proj_mma<<<dim3(DD / 128, MT / 128, 1), 128, GEMM_SMEM>>>(out);
}